// round 16
// baseline (speedup 1.0000x reference)
#include <cuda_runtime.h>
#include <cuda_fp16.h>
#include <cstdint>
#include <math.h>

// ---------------- problem constants ----------------
#define BB   4
#define NQ   8000
#define CC   256
#define NHD  8
#define NLV  4
#define NPT  4
#define DH   32
#define S_TOT 19947

#define MV (BB * S_TOT)   // 79788
#define MQ (BB * NQ)      // 32000

// ---------------- scratch ----------------
__device__ __half g_value_h[(size_t)MV * CC];        // projected value, fp16 (gather src)
__device__ float  g_qout [(size_t)MQ * 384];
__device__ __half g_v_hi [(size_t)MV * CC];
__device__ __half g_q_hi [(size_t)MQ * CC];
__device__ __half g_s_hi [(size_t)MQ * CC];
__device__ __half g_w_hi [65536 + 98304 + 65536];
__device__ float  g_qb[384];

// ---------------- helpers ----------------
__device__ __forceinline__ uint32_t smem_u32(const void* p) {
    uint32_t a;
    asm("{ .reg .u64 t; cvta.to.shared.u64 t, %1; cvt.u32.u64 %0, t; }" : "=r"(a) : "l"(p));
    return a;
}
__device__ __forceinline__ void ldsm4(uint32_t* r, uint32_t addr) {
    asm volatile("ldmatrix.sync.aligned.m8n8.x4.shared.b16 {%0,%1,%2,%3}, [%4];"
        : "=r"(r[0]), "=r"(r[1]), "=r"(r[2]), "=r"(r[3]) : "r"(addr));
}
__device__ __forceinline__ void mma_f32acc(float* c, const uint32_t* a, const uint32_t* b) {
    asm volatile(
        "mma.sync.aligned.m16n8k16.row.col.f32.f16.f16.f32 "
        "{%0,%1,%2,%3}, {%4,%5,%6,%7}, {%8,%9}, {%0,%1,%2,%3};"
        : "+f"(c[0]), "+f"(c[1]), "+f"(c[2]), "+f"(c[3])
        : "r"(a[0]), "r"(a[1]), "r"(a[2]), "r"(a[3]), "r"(b[0]), "r"(b[1]));
}
__device__ __forceinline__ void cp_async16(uint32_t dst, const void* src, uint32_t sz) {
    asm volatile("cp.async.cg.shared.global [%0], [%1], 16, %2;"
        :: "r"(dst), "l"(src), "r"(sz) : "memory");
}
#define CP_COMMIT() asm volatile("cp.async.commit_group;" ::: "memory")
#define CP_WAIT(n)  asm volatile("cp.async.wait_group %0;" :: "n"(n) : "memory")

// ---------------- mega conversion kernel (fp32 -> fp16) ----------------
#define NB_V  (MV / 4)
#define NB_Q  (MQ / 4)
#define NB_WV 64
#define NB_WO 64
#define NB_WA 32
#define NB_WU 64
#define NB_TOT (NB_V + NB_Q + NB_WV + NB_WO + NB_WA + NB_WU + 1)

struct ConvArgs {
    const float *vlv, *query, *w_val, *w_off, *w_attn, *w_out, *b_off, *b_attn;
};

__global__ void __launch_bounds__(256) convert_all_kernel(ConvArgs a)
{
    const int blk = blockIdx.x;
    const int tid = threadIdx.x;

    const float* src;
    uint2 *hi;
    int rel;

    if (blk < NB_V) {
        src = a.vlv; hi = (uint2*)g_v_hi; rel = blk;
    } else if (blk < NB_V + NB_Q) {
        src = a.query; hi = (uint2*)g_q_hi; rel = blk - NB_V;
    } else if (blk < NB_V + NB_Q + NB_WV) {
        src = a.w_val; hi = (uint2*)g_w_hi; rel = blk - (NB_V + NB_Q);
    } else if (blk < NB_V + NB_Q + NB_WV + NB_WO) {
        src = a.w_off; hi = (uint2*)(g_w_hi + 65536);
        rel = blk - (NB_V + NB_Q + NB_WV);
    } else if (blk < NB_V + NB_Q + NB_WV + NB_WO + NB_WA) {
        src = a.w_attn; hi = (uint2*)(g_w_hi + 131072);
        rel = blk - (NB_V + NB_Q + NB_WV + NB_WO);
    } else if (blk < NB_V + NB_Q + NB_WV + NB_WO + NB_WA + NB_WU) {
        src = a.w_out; hi = (uint2*)(g_w_hi + 163840);
        rel = blk - (NB_V + NB_Q + NB_WV + NB_WO + NB_WA);
    } else {
        for (int i = tid; i < 384; i += 256)
            g_qb[i] = (i < 256) ? a.b_off[i] : a.b_attn[i - 256];
        return;
    }

    const int i = rel * 256 + tid;
    const float4 v = ((const float4*)src)[i];
    __half h0 = __float2half_rn(v.x), h1 = __float2half_rn(v.y);
    __half h2 = __float2half_rn(v.z), h3 = __float2half_rn(v.w);
    uint2 hp;
    hp.x = (uint32_t)__half_as_ushort(h0) | ((uint32_t)__half_as_ushort(h1) << 16);
    hp.y = (uint32_t)__half_as_ushort(h2) | ((uint32_t)__half_as_ushort(h3) << 16);
    hi[i] = hp;
}

// ============ HMMA GEMM: fp16, 256 thr, 64x32 warp tile, ring-4 half-stages ============
// smem 64KB: A planes [0,32K) (two 16KB planes), B planes [32K,64K). bias @64K.
// slot s (0..3): plane = s>>1, half hb = (s&1)*64. One __syncthreads per half-stage.
struct GemmSeg {
    const __half *Ahi, *Bhi;
    const float* bias;
    void* C;
    int M, N, ntiles, tilesPerRow, outHalf;
};

__global__ void __launch_bounds__(256, 2) gemm_tc2_kernel(GemmSeg s0, GemmSeg s1)
{
    extern __shared__ char smraw[];
    char* sm = (char*)(((uintptr_t)smraw + 1023) & ~(uintptr_t)1023);
    const uint32_t su = smem_u32(sm);
    float* pbias = (float*)(sm + 65536);

    int t = blockIdx.x;
    const __half *Ahi, *Bhi;
    const float* bias;
    void* Cv;
    int M, N, tpr, outHalf;
    if (t < s0.ntiles) {
        Ahi = s0.Ahi; Bhi = s0.Bhi;
        bias = s0.bias; Cv = s0.C; M = s0.M; N = s0.N; tpr = s0.tilesPerRow; outHalf = s0.outHalf;
    } else {
        t -= s0.ntiles;
        Ahi = s1.Ahi; Bhi = s1.Bhi;
        bias = s1.bias; Cv = s1.C; M = s1.M; N = s1.N; tpr = s1.tilesPerRow; outHalf = s1.outHalf;
    }
    const int bm = (t / tpr) * 128;
    const int bn = (t % tpr) * 128;

    const int tid  = threadIdx.x;
    const int lane = tid & 31;
    const int warp = tid >> 5;
    const int wm = (warp >> 2) * 64;      // 2x4 layout: warp tile 64 rows x 32 cols
    const int wn = (warp & 3) * 32;

    if (tid < 128) pbias[tid] = bias[bn + tid];

    float acc[4][4][4];
#pragma unroll
    for (int i = 0; i < 4; i++)
#pragma unroll
        for (int j = 0; j < 4; j++)
#pragma unroll
            for (int k = 0; k < 4; k++) acc[i][j][k] = 0.f;

    const uint32_t mx = (uint32_t)((lane & 7) << 4);
    uint32_t aRow[4], bRow[2];
#pragma unroll
    for (int mi = 0; mi < 4; mi++)
        aRow[mi] = (uint32_t)((wm + mi * 16 + (lane & 15)) * 128);
    const uint32_t colA = (uint32_t)((lane >> 4) * 16);
#pragma unroll
    for (int nj2 = 0; nj2 < 2; nj2++)
        bRow[nj2] = (uint32_t)((wn + nj2 * 16 + (lane & 7) + ((lane >> 4) & 1) * 8) * 128);
    const uint32_t colB = (uint32_t)(((lane >> 3) & 1) * 16);

    // load one K-32 half-stage into ring slot (hs&3); 256 threads, 4 cp.async each
    auto load_half = [&](int hs) {
        const int s = hs & 3;
        const int hb = (s & 1) * 64;
        const uint32_t plane = (uint32_t)(s >> 1) * 16384u;
        const int ksrc = hs * 64;
#pragma unroll
        for (int pl = 0; pl < 2; pl++) {
            const __half* gsrc = (pl == 0) ? Ahi : Bhi;
            const bool isA = (pl == 0);
            const uint32_t pbase = su + (uint32_t)pl * 32768u + plane;
#pragma unroll
            for (int it = 0; it < 2; it++) {
                const int idx = it * 256 + tid;        // 0..511
                const int r = idx >> 2;
                const int c = idx & 3;
                const uint32_t doff = (uint32_t)(r * 128)
                    + (uint32_t)((hb + c * 16) ^ ((r & 7) << 4));
                const int grow = (isA ? bm : bn) + r;
                const uint32_t sz = (isA && grow >= M) ? 0u : 16u;
                const size_t soff = (size_t)grow * 512 + ksrc + c * 16;
                cp_async16(pbase + doff, (const char*)gsrc + soff, sz);
            }
        }
    };

    load_half(0); CP_COMMIT();
    load_half(1); CP_COMMIT();
    load_half(2); CP_COMMIT();

    for (int hs = 0; hs < 8; hs++) {
        if (hs < 6)      CP_WAIT(2);
        else if (hs == 6) CP_WAIT(1);
        else             CP_WAIT(0);
        __syncthreads();                   // single barrier per half-stage

        const int s = hs & 3;
        const uint32_t hb = (uint32_t)((s & 1) * 64);
        const uint32_t ap = su + (uint32_t)(s >> 1) * 16384u;
        const uint32_t bp = su + 32768u + (uint32_t)(s >> 1) * 16384u;
#pragma unroll
        for (int kk = 0; kk < 2; kk++) {
            uint32_t ah[4][4], bh[2][4];
            const uint32_t ca = (hb + (uint32_t)(kk * 32) + colA) ^ mx;
            const uint32_t cb = (hb + (uint32_t)(kk * 32) + colB) ^ mx;
#pragma unroll
            for (int mi = 0; mi < 4; mi++)
                ldsm4(ah[mi], ap + aRow[mi] + ca);
#pragma unroll
            for (int nj2 = 0; nj2 < 2; nj2++)
                ldsm4(bh[nj2], bp + bRow[nj2] + cb);
#pragma unroll
            for (int mi = 0; mi < 4; mi++)
#pragma unroll
                for (int nj = 0; nj < 4; nj++)
                    mma_f32acc(acc[mi][nj], ah[mi], &bh[nj >> 1][(nj & 1) * 2]);
        }
        if (hs < 5) { load_half(hs + 3); CP_COMMIT(); }
    }

    const int r0 = lane >> 2;
    const int c0 = (lane & 3) * 2;
#pragma unroll
    for (int mi = 0; mi < 4; mi++) {
        const int gm = bm + wm + mi * 16 + r0;
#pragma unroll
        for (int half = 0; half < 2; half++) {
            const int gmr = gm + half * 8;
            if (gmr < M) {
                if (outHalf) {
                    __half* op = (__half*)Cv + (size_t)gmr * N + bn;
#pragma unroll
                    for (int nj = 0; nj < 4; nj++) {
                        const int cl = wn + nj * 8 + c0;
                        *(__half2*)(op + cl) = __floats2half2_rn(
                            acc[mi][nj][half * 2 + 0] + pbias[cl],
                            acc[mi][nj][half * 2 + 1] + pbias[cl + 1]);
                    }
                } else {
                    float* op = (float*)Cv + (size_t)gmr * N + bn;
#pragma unroll
                    for (int nj = 0; nj < 4; nj++) {
                        const int cl = wn + nj * 8 + c0;
                        float2 o;
                        o.x = acc[mi][nj][half * 2 + 0] + pbias[cl];
                        o.y = acc[mi][nj][half * 2 + 1] + pbias[cl + 1];
                        *(float2*)(op + cl) = o;
                    }
                }
            }
        }
    }
}

// ---------------- sampling: branchless clamped gather --------------------
// owner lanes 0..15: clamp corners, zero invalid weights (pre-multiplied by aw),
// pack base|dx|dy. gather: 5 shuffles + 4 unconditional uint2 loads per level.
__global__ void __launch_bounds__(256) sample_kernel(
    const float* __restrict__ ref)
{
    constexpr int LH[4]  = {100, 50, 25, 13};
    constexpr int LW[4]  = {150, 75, 38, 19};
    constexpr int LST[4] = {0, 15000, 18750, 19700};

    const int warp = (blockIdx.x * blockDim.x + threadIdx.x) >> 5;
    const int lane = threadIdx.x & 31;
    if (warp >= BB * NQ * NHD) return;

    const int h  = warp % NHD;
    const int bq = warp / NHD;
    const int b  = bq / NQ;
    const int sl = (lane >> 2) & 3;

    const float* qrow = g_qout + (size_t)bq * 384;

    // softmax over 16 logits, one per lane
    const float* logit = qrow + 256 + h * 16;
    float lg = (lane < 16) ? logit[lane] : -1e30f;
    float mxv = lg;
#pragma unroll
    for (int o = 8; o; o >>= 1) mxv = fmaxf(mxv, __shfl_xor_sync(0xffffffffu, mxv, o, 16));
    float ev = __expf(lg - mxv);
    float sum = ev;
#pragma unroll
    for (int o = 8; o; o >>= 1) sum += __shfl_xor_sync(0xffffffffu, sum, o, 16);
    const float aw = ev / sum;

    // owner-side: coords, clamped corner packing, zeroed weights
    const float2 off2 = ((const float2*)(qrow + h * 32))[lane & 15];
    const float2 rxy  = ((const float2*)(ref + (size_t)bq * 8))[sl];
    const int Wo = LW[sl], Ho = LH[sl];
    const float fW = (float)Wo, fH = (float)Ho;
    const float x = (rxy.x + off2.x / fW) * fW - 0.5f;
    const float y = (rxy.y + off2.y / fH) * fH - 0.5f;
    const float x0f = floorf(x), y0f = floorf(y);
    const int ix0 = (int)x0f, iy0 = (int)y0f;
    const float wx1 = x - x0f, wy1 = y - y0f;
    const float wx0 = 1.f - wx1, wy0 = 1.f - wy1;

    const bool vx0 = (unsigned)ix0 < (unsigned)Wo;
    const bool vx1 = (unsigned)(ix0 + 1) < (unsigned)Wo;
    const bool vy0 = (unsigned)iy0 < (unsigned)Ho;
    const bool vy1 = (unsigned)(iy0 + 1) < (unsigned)Ho;
    const int cx0 = min(max(ix0, 0), Wo - 1);
    const int cx1 = min(max(ix0 + 1, 0), Wo - 1);
    const int cy0 = min(max(iy0, 0), Ho - 1);
    const int cy1 = min(max(iy0 + 1, 0), Ho - 1);
    const int pack_o = (cy0 * Wo + cx0) | ((cx1 - cx0) << 14) | ((cy1 - cy0) << 15);
    const float w00_o = (vx0 && vy0) ? wx0 * wy0 * aw : 0.f;
    const float w10_o = (vx1 && vy0) ? wx1 * wy0 * aw : 0.f;
    const float w01_o = (vx0 && vy1) ? wx0 * wy1 * aw : 0.f;
    const float w11_o = (vx1 && vy1) ? wx1 * wy1 * aw : 0.f;

    const int grp  = lane >> 3;          // sample-in-level (0..3)
    const int chan = (lane & 7) * 4;     // channel quad
    float a0 = 0.f, a1 = 0.f, a2 = 0.f, a3 = 0.f;

#pragma unroll
    for (int l = 0; l < 4; l++) {
        const int W = LW[l];
        const __half* vbase = g_value_h
            + ((size_t)(b * S_TOT + LST[l]) * NHD + h) * DH + chan;
        const int src = l * 4 + grp;
        const int   pk  = __shfl_sync(0xffffffffu, pack_o, src);
        const float w00 = __shfl_sync(0xffffffffu, w00_o,  src);
        const float w10 = __shfl_sync(0xffffffffu, w10_o,  src);
        const float w01 = __shfl_sync(0xffffffffu, w01_o,  src);
        const float w11 = __shfl_sync(0xffffffffu, w11_o,  src);
        const int base = pk & 0x3fff;
        const int ox = ((pk >> 14) & 1) << 8;           // +256 halves if dx
        const int oy = (pk & 0x8000) ? W * 256 : 0;     // +W row if dy
        const __half* p = vbase + (ptrdiff_t)base * 256;

        { const uint2 v = *(const uint2*)p;
          const float2 f01 = __half22float2(*(const __half2*)&v.x);
          const float2 f23 = __half22float2(*(const __half2*)&v.y);
          a0 = fmaf(w00, f01.x, a0); a1 = fmaf(w00, f01.y, a1);
          a2 = fmaf(w00, f23.x, a2); a3 = fmaf(w00, f23.y, a3); }
        { const uint2 v = *(const uint2*)(p + ox);
          const float2 f01 = __half22float2(*(const __half2*)&v.x);
          const float2 f23 = __half22float2(*(const __half2*)&v.y);
          a0 = fmaf(w10, f01.x, a0); a1 = fmaf(w10, f01.y, a1);
          a2 = fmaf(w10, f23.x, a2); a3 = fmaf(w10, f23.y, a3); }
        { const uint2 v = *(const uint2*)(p + oy);
          const float2 f01 = __half22float2(*(const __half2*)&v.x);
          const float2 f23 = __half22float2(*(const __half2*)&v.y);
          a0 = fmaf(w01, f01.x, a0); a1 = fmaf(w01, f01.y, a1);
          a2 = fmaf(w01, f23.x, a2); a3 = fmaf(w01, f23.y, a3); }
        { const uint2 v = *(const uint2*)(p + ox + oy);
          const float2 f01 = __half22float2(*(const __half2*)&v.x);
          const float2 f23 = __half22float2(*(const __half2*)&v.y);
          a0 = fmaf(w11, f01.x, a0); a1 = fmaf(w11, f01.y, a1);
          a2 = fmaf(w11, f23.x, a2); a3 = fmaf(w11, f23.y, a3); }
    }
#pragma unroll
    for (int o = 8; o <= 16; o <<= 1) {
        a0 += __shfl_xor_sync(0xffffffffu, a0, o);
        a1 += __shfl_xor_sync(0xffffffffu, a1, o);
        a2 += __shfl_xor_sync(0xffffffffu, a2, o);
        a3 += __shfl_xor_sync(0xffffffffu, a3, o);
    }

    if (lane < 8) {
        __half h0 = __float2half_rn(a0), h1 = __float2half_rn(a1);
        __half h2 = __float2half_rn(a2), h3 = __float2half_rn(a3);
        uint2 hp;
        hp.x = (uint32_t)__half_as_ushort(h0) | ((uint32_t)__half_as_ushort(h1) << 16);
        hp.y = (uint32_t)__half_as_ushort(h2) | ((uint32_t)__half_as_ushort(h3) << 16);
        const size_t q2 = (size_t)(bq * NHD + h) * 8 + (lane & 7);
        ((uint2*)g_s_hi)[q2] = hp;
    }
}

// ---------------- launch ----------------
#define GEMM_SMEM_BYTES 66048

extern "C" void kernel_launch(void* const* d_in, const int* in_sizes, int n_in,
                              void* d_out, int out_size)
{
    (void)in_sizes; (void)n_in; (void)out_size;
    const float* query  = (const float*)d_in[0];
    const float* vlv    = (const float*)d_in[1];
    const float* refpts = (const float*)d_in[2];
    const float* W_off  = (const float*)d_in[4];
    const float* b_off  = (const float*)d_in[5];
    const float* W_attn = (const float*)d_in[6];
    const float* b_attn = (const float*)d_in[7];
    const float* W_val  = (const float*)d_in[8];
    const float* b_val  = (const float*)d_in[9];
    const float* W_out  = (const float*)d_in[10];
    const float* b_out  = (const float*)d_in[11];
    float* out = (float*)d_out;

    cudaFuncSetAttribute(gemm_tc2_kernel,
                         cudaFuncAttributeMaxDynamicSharedMemorySize, GEMM_SMEM_BYTES);

    float *p_qout, *p_qb;
    __half *p_valh, *p_vhi, *p_qhi, *p_shi, *p_whi;
    cudaGetSymbolAddress((void**)&p_valh,  g_value_h);
    cudaGetSymbolAddress((void**)&p_qout,  g_qout);
    cudaGetSymbolAddress((void**)&p_qb,    g_qb);
    cudaGetSymbolAddress((void**)&p_vhi,   g_v_hi);
    cudaGetSymbolAddress((void**)&p_qhi,   g_q_hi);
    cudaGetSymbolAddress((void**)&p_shi,   g_s_hi);
    cudaGetSymbolAddress((void**)&p_whi,   g_w_hi);

    __half *wv_hi = p_whi;
    __half *qw_hi = p_whi + 65536;
    __half *wu_hi = p_whi + 163840;

    {
        ConvArgs ca;
        ca.vlv = vlv; ca.query = query;
        ca.w_val = W_val; ca.w_off = W_off; ca.w_attn = W_attn; ca.w_out = W_out;
        ca.b_off = b_off; ca.b_attn = b_attn;
        convert_all_kernel<<<NB_TOT, 256>>>(ca);
    }

    {
        GemmSeg sv, sq;
        sv.Ahi = p_vhi; sv.Bhi = wv_hi;
        sv.bias = b_val; sv.C = p_valh; sv.M = MV; sv.N = 256;
        sv.tilesPerRow = 2; sv.ntiles = ((MV + 127) / 128) * 2; sv.outHalf = 1;
        sq.Ahi = p_qhi; sq.Bhi = qw_hi;
        sq.bias = p_qb; sq.C = p_qout; sq.M = MQ; sq.N = 384;
        sq.tilesPerRow = 3; sq.ntiles = (MQ / 128) * 3; sq.outHalf = 0;
        gemm_tc2_kernel<<<sv.ntiles + sq.ntiles, 256, GEMM_SMEM_BYTES>>>(sv, sq);
    }

    {
        const int nwarp = BB * NQ * NHD;
        sample_kernel<<<(nwarp * 32 + 255) / 256, 256>>>(refpts);
    }

    {
        GemmSeg so, dummy;
        so.Ahi = p_shi; so.Bhi = wu_hi;
        so.bias = b_out; so.C = out; so.M = MQ; so.N = 256;
        so.tilesPerRow = 2; so.ntiles = (MQ / 128) * 2; so.outHalf = 0;
        dummy = so; dummy.ntiles = 0;
        gemm_tc2_kernel<<<so.ntiles, 256, GEMM_SMEM_BYTES>>>(so, dummy);
    }
}

// round 17
// speedup vs baseline: 1.1090x; 1.1090x over previous
#include <cuda_runtime.h>
#include <cuda_fp16.h>
#include <cstdint>
#include <math.h>

// ---------------- problem constants ----------------
#define BB   4
#define NQ   8000
#define CC   256
#define NHD  8
#define NLV  4
#define NPT  4
#define DH   32
#define S_TOT 19947

#define MV (BB * S_TOT)   // 79788
#define MQ (BB * NQ)      // 32000

// ---------------- scratch ----------------
__device__ __half g_value_h[(size_t)MV * CC];        // projected value, fp16 (gather src)
__device__ float  g_qout [(size_t)MQ * 384];
__device__ __half g_v_hi [(size_t)MV * CC];
__device__ __half g_q_hi [(size_t)MQ * CC];
__device__ __half g_s_hi [(size_t)MQ * CC];
__device__ __half g_w_hi [65536 + 98304 + 65536];
__device__ float  g_qb[384];

// ---------------- helpers ----------------
__device__ __forceinline__ uint32_t smem_u32(const void* p) {
    uint32_t a;
    asm("{ .reg .u64 t; cvta.to.shared.u64 t, %1; cvt.u32.u64 %0, t; }" : "=r"(a) : "l"(p));
    return a;
}
__device__ __forceinline__ void ldsm4(uint32_t* r, uint32_t addr) {
    asm volatile("ldmatrix.sync.aligned.m8n8.x4.shared.b16 {%0,%1,%2,%3}, [%4];"
        : "=r"(r[0]), "=r"(r[1]), "=r"(r[2]), "=r"(r[3]) : "r"(addr));
}
__device__ __forceinline__ void mma_f32acc(float* c, const uint32_t* a, const uint32_t* b) {
    asm volatile(
        "mma.sync.aligned.m16n8k16.row.col.f32.f16.f16.f32 "
        "{%0,%1,%2,%3}, {%4,%5,%6,%7}, {%8,%9}, {%0,%1,%2,%3};"
        : "+f"(c[0]), "+f"(c[1]), "+f"(c[2]), "+f"(c[3])
        : "r"(a[0]), "r"(a[1]), "r"(a[2]), "r"(a[3]), "r"(b[0]), "r"(b[1]));
}
__device__ __forceinline__ void cp_async16(uint32_t dst, const void* src, uint32_t sz) {
    asm volatile("cp.async.cg.shared.global [%0], [%1], 16, %2;"
        :: "r"(dst), "l"(src), "r"(sz) : "memory");
}
#define CP_COMMIT() asm volatile("cp.async.commit_group;" ::: "memory")
#define CP_WAIT(n)  asm volatile("cp.async.wait_group %0;" :: "n"(n) : "memory")

// ---------------- mega conversion kernel (fp32 -> fp16) ----------------
#define NB_V  (MV / 4)
#define NB_Q  (MQ / 4)
#define NB_WV 64
#define NB_WO 64
#define NB_WA 32
#define NB_WU 64
#define NB_TOT (NB_V + NB_Q + NB_WV + NB_WO + NB_WA + NB_WU + 1)

struct ConvArgs {
    const float *vlv, *query, *w_val, *w_off, *w_attn, *w_out, *b_off, *b_attn;
};

__global__ void __launch_bounds__(256) convert_all_kernel(ConvArgs a)
{
    const int blk = blockIdx.x;
    const int tid = threadIdx.x;

    const float* src;
    uint2 *hi;
    int rel;

    if (blk < NB_V) {
        src = a.vlv; hi = (uint2*)g_v_hi; rel = blk;
    } else if (blk < NB_V + NB_Q) {
        src = a.query; hi = (uint2*)g_q_hi; rel = blk - NB_V;
    } else if (blk < NB_V + NB_Q + NB_WV) {
        src = a.w_val; hi = (uint2*)g_w_hi; rel = blk - (NB_V + NB_Q);
    } else if (blk < NB_V + NB_Q + NB_WV + NB_WO) {
        src = a.w_off; hi = (uint2*)(g_w_hi + 65536);
        rel = blk - (NB_V + NB_Q + NB_WV);
    } else if (blk < NB_V + NB_Q + NB_WV + NB_WO + NB_WA) {
        src = a.w_attn; hi = (uint2*)(g_w_hi + 131072);
        rel = blk - (NB_V + NB_Q + NB_WV + NB_WO);
    } else if (blk < NB_V + NB_Q + NB_WV + NB_WO + NB_WA + NB_WU) {
        src = a.w_out; hi = (uint2*)(g_w_hi + 163840);
        rel = blk - (NB_V + NB_Q + NB_WV + NB_WO + NB_WA);
    } else {
        for (int i = tid; i < 384; i += 256)
            g_qb[i] = (i < 256) ? a.b_off[i] : a.b_attn[i - 256];
        return;
    }

    const int i = rel * 256 + tid;
    const float4 v = ((const float4*)src)[i];
    __half h0 = __float2half_rn(v.x), h1 = __float2half_rn(v.y);
    __half h2 = __float2half_rn(v.z), h3 = __float2half_rn(v.w);
    uint2 hp;
    hp.x = (uint32_t)__half_as_ushort(h0) | ((uint32_t)__half_as_ushort(h1) << 16);
    hp.y = (uint32_t)__half_as_ushort(h2) | ((uint32_t)__half_as_ushort(h3) << 16);
    hi[i] = hp;
}

// ============ HMMA GEMM: fp16, 256 thr, 64x32 warp tile, 2 CTAs/SM (R14) ============
struct GemmSeg {
    const __half *Ahi, *Bhi;
    const float* bias;
    void* C;
    int M, N, ntiles, tilesPerRow, outHalf;
};

__global__ void __launch_bounds__(256, 2) gemm_tc2_kernel(GemmSeg s0, GemmSeg s1)
{
    extern __shared__ char smraw[];
    char* sm = (char*)(((uintptr_t)smraw + 1023) & ~(uintptr_t)1023);
    const uint32_t su = smem_u32(sm);
    float* pbias = (float*)(sm + 32768);

    int t = blockIdx.x;
    const __half *Ahi, *Bhi;
    const float* bias;
    void* Cv;
    int M, N, tpr, outHalf;
    if (t < s0.ntiles) {
        Ahi = s0.Ahi; Bhi = s0.Bhi;
        bias = s0.bias; Cv = s0.C; M = s0.M; N = s0.N; tpr = s0.tilesPerRow; outHalf = s0.outHalf;
    } else {
        t -= s0.ntiles;
        Ahi = s1.Ahi; Bhi = s1.Bhi;
        bias = s1.bias; Cv = s1.C; M = s1.M; N = s1.N; tpr = s1.tilesPerRow; outHalf = s1.outHalf;
    }
    const int bm = (t / tpr) * 128;
    const int bn = (t % tpr) * 128;

    const int tid  = threadIdx.x;
    const int lane = tid & 31;
    const int warp = tid >> 5;
    const int wm = (warp >> 2) * 64;
    const int wn = (warp & 3) * 32;

    if (tid < 128) pbias[tid] = bias[bn + tid];

    float acc[4][4][4];
#pragma unroll
    for (int i = 0; i < 4; i++)
#pragma unroll
        for (int j = 0; j < 4; j++)
#pragma unroll
            for (int k = 0; k < 4; k++) acc[i][j][k] = 0.f;

    const uint32_t mx = (uint32_t)((lane & 7) << 4);
    uint32_t aRow[4], bRow[2];
#pragma unroll
    for (int mi = 0; mi < 4; mi++)
        aRow[mi] = (uint32_t)((wm + mi * 16 + (lane & 15)) * 128);
    const uint32_t colA = (uint32_t)((lane >> 4) * 16);
#pragma unroll
    for (int nj2 = 0; nj2 < 2; nj2++)
        bRow[nj2] = (uint32_t)((wn + nj2 * 16 + (lane & 7) + ((lane >> 4) & 1) * 8) * 128);
    const uint32_t colB = (uint32_t)(((lane >> 3) & 1) * 16);

    auto load_half = [&](int hs) {
        const int hb = (hs & 1) * 64;
        const int ksrc = hs * 64;
#pragma unroll
        for (int pl = 0; pl < 2; pl++) {
            const __half* gsrc = (pl == 0) ? Ahi : Bhi;
            const bool isA = (pl == 0);
            const uint32_t pbase = su + (uint32_t)pl * 16384u;
#pragma unroll
            for (int it = 0; it < 2; it++) {
                const int idx = it * 256 + tid;
                const int r = idx >> 2;
                const int c = idx & 3;
                const uint32_t doff = (uint32_t)(r * 128)
                    + (uint32_t)((hb + c * 16) ^ ((r & 7) << 4));
                const int grow = (isA ? bm : bn) + r;
                const uint32_t sz = (isA && grow >= M) ? 0u : 16u;
                const size_t soff = (size_t)grow * 512 + ksrc + c * 16;
                cp_async16(pbase + doff, (const char*)gsrc + soff, sz);
            }
        }
    };

    load_half(0); CP_COMMIT();
    load_half(1); CP_COMMIT();

    for (int hs = 0; hs < 8; hs++) {
        if (hs < 7) CP_WAIT(1); else CP_WAIT(0);
        __syncthreads();

        const uint32_t hb = (uint32_t)((hs & 1) * 64);
#pragma unroll
        for (int kk = 0; kk < 2; kk++) {
            uint32_t ah[4][4], bh[2][4];
            const uint32_t ca = (hb + (uint32_t)(kk * 32) + colA) ^ mx;
            const uint32_t cb = (hb + (uint32_t)(kk * 32) + colB) ^ mx;
#pragma unroll
            for (int mi = 0; mi < 4; mi++)
                ldsm4(ah[mi], su + aRow[mi] + ca);
#pragma unroll
            for (int nj2 = 0; nj2 < 2; nj2++)
                ldsm4(bh[nj2], su + 16384 + bRow[nj2] + cb);
#pragma unroll
            for (int mi = 0; mi < 4; mi++)
#pragma unroll
                for (int nj = 0; nj < 4; nj++)
                    mma_f32acc(acc[mi][nj], ah[mi], &bh[nj >> 1][(nj & 1) * 2]);
        }
        __syncthreads();
        if (hs < 6) { load_half(hs + 2); CP_COMMIT(); }
    }

    const int r0 = lane >> 2;
    const int c0 = (lane & 3) * 2;
#pragma unroll
    for (int mi = 0; mi < 4; mi++) {
        const int gm = bm + wm + mi * 16 + r0;
#pragma unroll
        for (int half = 0; half < 2; half++) {
            const int gmr = gm + half * 8;
            if (gmr < M) {
                if (outHalf) {
                    __half* op = (__half*)Cv + (size_t)gmr * N + bn;
#pragma unroll
                    for (int nj = 0; nj < 4; nj++) {
                        const int cl = wn + nj * 8 + c0;
                        *(__half2*)(op + cl) = __floats2half2_rn(
                            acc[mi][nj][half * 2 + 0] + pbias[cl],
                            acc[mi][nj][half * 2 + 1] + pbias[cl + 1]);
                    }
                } else {
                    float* op = (float*)Cv + (size_t)gmr * N + bn;
#pragma unroll
                    for (int nj = 0; nj < 4; nj++) {
                        const int cl = wn + nj * 8 + c0;
                        float2 o;
                        o.x = acc[mi][nj][half * 2 + 0] + pbias[cl];
                        o.y = acc[mi][nj][half * 2 + 1] + pbias[cl + 1];
                        *(float2*)(op + cl) = o;
                    }
                }
            }
        }
    }
}

// ---------------- sampling: 2 heads per warp -----------------------------
// owner phase (all 32 lanes busy): lane = (head lane>>4, sample lane&15).
// gather: 8 (head,level) iterations; lane = (sample grp lane>>3, chan quad).
__global__ void __launch_bounds__(256) sample_kernel(
    const float* __restrict__ ref)
{
    constexpr int LH[4]  = {100, 50, 25, 13};
    constexpr int LW[4]  = {150, 75, 38, 19};
    constexpr int LST[4] = {0, 15000, 18750, 19700};

    const int warp = (blockIdx.x * blockDim.x + threadIdx.x) >> 5;
    const int lane = threadIdx.x & 31;
    if (warp >= BB * NQ * (NHD / 2)) return;

    const int hp = warp & 3;          // head pair
    const int bq = warp >> 2;
    const int b  = bq / NQ;

    const int hsel = lane >> 4;       // which head of the pair (owner phase)
    const int s    = lane & 15;       // sample index
    const int h    = hp * 2 + hsel;
    const int sl   = s >> 2;          // sample's level

    const float* qrow = g_qout + (size_t)bq * 384;

    // softmax over 16 logits per head (width-16 shuffles stay in-half)
    float lg = qrow[256 + h * 16 + s];
    float mxv = lg;
#pragma unroll
    for (int o = 8; o; o >>= 1) mxv = fmaxf(mxv, __shfl_xor_sync(0xffffffffu, mxv, o, 16));
    float ev = __expf(lg - mxv);
    float sum = ev;
#pragma unroll
    for (int o = 8; o; o >>= 1) sum += __shfl_xor_sync(0xffffffffu, sum, o, 16);
    const float aw = ev / sum;

    // per-lane sample coords (all 32 lanes meaningful)
    const float2 off2 = ((const float2*)(qrow + h * 32))[s];
    const float2 rxy  = ((const float2*)(ref + (size_t)bq * 8))[sl];
    const float fW = (float)LW[sl], fH = (float)LH[sl];
    const float x = (rxy.x + off2.x / fW) * fW - 0.5f;
    const float y = (rxy.y + off2.y / fH) * fH - 0.5f;
    const float x0f = floorf(x), y0f = floorf(y);
    const float wx1 = x - x0f, wy1 = y - y0f;
    const int pk = (((int)y0f) << 16) | (((int)x0f) & 0xffff);
    const float wy0a_o = (1.f - wy1) * aw;
    const float wy1a_o = wy1 * aw;

    const int grp  = lane >> 3;          // sample-in-level (0..3)
    const int chan = (lane & 7) * 4;     // channel quad
    float acc[2][4];
#pragma unroll
    for (int i = 0; i < 2; i++)
#pragma unroll
        for (int j = 0; j < 4; j++) acc[i][j] = 0.f;

#pragma unroll
    for (int hg = 0; hg < 2; hg++) {
        const int hcur = hp * 2 + hg;
#pragma unroll
        for (int l = 0; l < 4; l++) {
            const int W = LW[l], H = LH[l];
            const __half* vbase = g_value_h
                + ((size_t)(b * S_TOT + LST[l]) * NHD + hcur) * DH + chan;
            const int src = hg * 16 + l * 4 + grp;
            const int   bpk  = __shfl_sync(0xffffffffu, pk,     src);
            const float bwx  = __shfl_sync(0xffffffffu, wx1,    src);
            const float wy0a = __shfl_sync(0xffffffffu, wy0a_o, src);
            const float wy1a = __shfl_sync(0xffffffffu, wy1a_o, src);
            const int bix = (int)(short)(bpk & 0xffff);
            const int biy = bpk >> 16;
            const float wx0 = 1.f - bwx;
            const bool xi0 = (unsigned)bix < (unsigned)W;
            const bool xi1 = (unsigned)(bix + 1) < (unsigned)W;
            const bool yi0 = (unsigned)biy < (unsigned)H;
            const bool yi1 = (unsigned)(biy + 1) < (unsigned)H;
            const __half* pp0 = vbase + (ptrdiff_t)(biy * W + bix) * 256;
            float* a = acc[hg];
            if (yi0 && xi0) { const uint2 v = *(const uint2*)pp0;
                const float2 f01 = __half22float2(*(const __half2*)&v.x);
                const float2 f23 = __half22float2(*(const __half2*)&v.y);
                const float w = wx0 * wy0a;
                a[0] = fmaf(w, f01.x, a[0]); a[1] = fmaf(w, f01.y, a[1]);
                a[2] = fmaf(w, f23.x, a[2]); a[3] = fmaf(w, f23.y, a[3]); }
            if (yi0 && xi1) { const uint2 v = *(const uint2*)(pp0 + 256);
                const float2 f01 = __half22float2(*(const __half2*)&v.x);
                const float2 f23 = __half22float2(*(const __half2*)&v.y);
                const float w = bwx * wy0a;
                a[0] = fmaf(w, f01.x, a[0]); a[1] = fmaf(w, f01.y, a[1]);
                a[2] = fmaf(w, f23.x, a[2]); a[3] = fmaf(w, f23.y, a[3]); }
            if (yi1 && xi0) { const uint2 v = *(const uint2*)(pp0 + W * 256);
                const float2 f01 = __half22float2(*(const __half2*)&v.x);
                const float2 f23 = __half22float2(*(const __half2*)&v.y);
                const float w = wx0 * wy1a;
                a[0] = fmaf(w, f01.x, a[0]); a[1] = fmaf(w, f01.y, a[1]);
                a[2] = fmaf(w, f23.x, a[2]); a[3] = fmaf(w, f23.y, a[3]); }
            if (yi1 && xi1) { const uint2 v = *(const uint2*)(pp0 + W * 256 + 256);
                const float2 f01 = __half22float2(*(const __half2*)&v.x);
                const float2 f23 = __half22float2(*(const __half2*)&v.y);
                const float w = bwx * wy1a;
                a[0] = fmaf(w, f01.x, a[0]); a[1] = fmaf(w, f01.y, a[1]);
                a[2] = fmaf(w, f23.x, a[2]); a[3] = fmaf(w, f23.y, a[3]); }
        }
    }
    // reduce each head's accumulators over the 4 sample-groups (lane bits 3,4)
#pragma unroll
    for (int hg = 0; hg < 2; hg++) {
#pragma unroll
        for (int o = 8; o <= 16; o <<= 1) {
            acc[hg][0] += __shfl_xor_sync(0xffffffffu, acc[hg][0], o);
            acc[hg][1] += __shfl_xor_sync(0xffffffffu, acc[hg][1], o);
            acc[hg][2] += __shfl_xor_sync(0xffffffffu, acc[hg][2], o);
            acc[hg][3] += __shfl_xor_sync(0xffffffffu, acc[hg][3], o);
        }
    }

    // lanes 0-7 store head0's 8 channel quads; lanes 8-15 store head1's
    const int sh = lane >> 3;
    if (sh < 2) {
        const float r0 = (sh == 0) ? acc[0][0] : acc[1][0];
        const float r1 = (sh == 0) ? acc[0][1] : acc[1][1];
        const float r2 = (sh == 0) ? acc[0][2] : acc[1][2];
        const float r3 = (sh == 0) ? acc[0][3] : acc[1][3];
        __half h0 = __float2half_rn(r0), h1 = __float2half_rn(r1);
        __half h2 = __float2half_rn(r2), h3 = __float2half_rn(r3);
        uint2 hpk;
        hpk.x = (uint32_t)__half_as_ushort(h0) | ((uint32_t)__half_as_ushort(h1) << 16);
        hpk.y = (uint32_t)__half_as_ushort(h2) | ((uint32_t)__half_as_ushort(h3) << 16);
        const int hst = hp * 2 + sh;
        const size_t q2 = (size_t)(bq * NHD + hst) * 8 + (lane & 7);
        ((uint2*)g_s_hi)[q2] = hpk;
    }
}

// ---------------- launch ----------------
#define GEMM_SMEM_BYTES 34304

extern "C" void kernel_launch(void* const* d_in, const int* in_sizes, int n_in,
                              void* d_out, int out_size)
{
    (void)in_sizes; (void)n_in; (void)out_size;
    const float* query  = (const float*)d_in[0];
    const float* vlv    = (const float*)d_in[1];
    const float* refpts = (const float*)d_in[2];
    const float* W_off  = (const float*)d_in[4];
    const float* b_off  = (const float*)d_in[5];
    const float* W_attn = (const float*)d_in[6];
    const float* b_attn = (const float*)d_in[7];
    const float* W_val  = (const float*)d_in[8];
    const float* b_val  = (const float*)d_in[9];
    const float* W_out  = (const float*)d_in[10];
    const float* b_out  = (const float*)d_in[11];
    float* out = (float*)d_out;

    cudaFuncSetAttribute(gemm_tc2_kernel,
                         cudaFuncAttributeMaxDynamicSharedMemorySize, GEMM_SMEM_BYTES);

    float *p_qout, *p_qb;
    __half *p_valh, *p_vhi, *p_qhi, *p_shi, *p_whi;
    cudaGetSymbolAddress((void**)&p_valh,  g_value_h);
    cudaGetSymbolAddress((void**)&p_qout,  g_qout);
    cudaGetSymbolAddress((void**)&p_qb,    g_qb);
    cudaGetSymbolAddress((void**)&p_vhi,   g_v_hi);
    cudaGetSymbolAddress((void**)&p_qhi,   g_q_hi);
    cudaGetSymbolAddress((void**)&p_shi,   g_s_hi);
    cudaGetSymbolAddress((void**)&p_whi,   g_w_hi);

    __half *wv_hi = p_whi;
    __half *qw_hi = p_whi + 65536;
    __half *wu_hi = p_whi + 163840;

    {
        ConvArgs ca;
        ca.vlv = vlv; ca.query = query;
        ca.w_val = W_val; ca.w_off = W_off; ca.w_attn = W_attn; ca.w_out = W_out;
        ca.b_off = b_off; ca.b_attn = b_attn;
        convert_all_kernel<<<NB_TOT, 256>>>(ca);
    }

    {
        GemmSeg sv, sq;
        sv.Ahi = p_vhi; sv.Bhi = wv_hi;
        sv.bias = b_val; sv.C = p_valh; sv.M = MV; sv.N = 256;
        sv.tilesPerRow = 2; sv.ntiles = ((MV + 127) / 128) * 2; sv.outHalf = 1;
        sq.Ahi = p_qhi; sq.Bhi = qw_hi;
        sq.bias = p_qb; sq.C = p_qout; sq.M = MQ; sq.N = 384;
        sq.tilesPerRow = 3; sq.ntiles = (MQ / 128) * 3; sq.outHalf = 0;
        gemm_tc2_kernel<<<sv.ntiles + sq.ntiles, 256, GEMM_SMEM_BYTES>>>(sv, sq);
    }

    {
        const int nwarp = BB * NQ * (NHD / 2);       // 128000
        sample_kernel<<<(nwarp * 32 + 255) / 256, 256>>>(refpts);
    }

    {
        GemmSeg so, dummy;
        so.Ahi = p_shi; so.Bhi = wu_hi;
        so.bias = b_out; so.C = out; so.M = MQ; so.N = 256;
        so.tilesPerRow = 2; so.ntiles = (MQ / 128) * 2; so.outHalf = 0;
        dummy = so; dummy.ntiles = 0;
        gemm_tc2_kernel<<<so.ntiles, 256, GEMM_SMEM_BYTES>>>(so, dummy);
    }
}